// round 3
// baseline (speedup 1.0000x reference)
#include <cuda_runtime.h>
#include <math.h>

// Problem constants
#define BB   64
#define NCC  20
#define KK   150
#define CC   2048
#define TL   750
#define T_NCE 0.07f
#define EPSF  1e-7f

// -------- scratch (device globals; no allocation) --------
__device__ float g_qn [2][BB*CC];   // pass1: sums of HA/HB, then normalized in place
__device__ float g_SE [2][BB*CC];   // pass2: sum over K of scanned tensor (i=0 scans EB, i=1 scans EA)
__device__ float g_dot[2][BB*KK];   // qn[i] . neg_i[n,k,:]
__device__ float g_nrm[2][BB*KK];   // ||neg_i[n,k,:]||^2
__device__ float g_lpos[2][BB];
__device__ float g_acc[8];          // 0:cls 1:rel_s 2:rel_d 3:act_wabsm 4:act_sq

// -------- zero the atomically-accumulated scratch (graph replays!) --------
__global__ void k_zero() {
    int i = blockIdx.x * 256 + threadIdx.x;
    if (i < 2*BB*CC)  ((float*)g_SE)[i]  = 0.f;
    if (i < 2*BB*KK) { ((float*)g_dot)[i] = 0.f; ((float*)g_nrm)[i] = 0.f; }
    if (i < 8)        g_acc[i] = 0.f;
}

// -------- pass 1: column sums of HA, HB over K --------
// 65536 threads: (tensor, n, c4). Coalesced float4 loads, stride C between k's.
__global__ void k_qsum(const float* __restrict__ HA, const float* __restrict__ HB) {
    int id  = blockIdx.x * 256 + threadIdx.x;      // 0..65535
    int t   = id >> 15;
    int rem = id & 32767;
    int n   = rem >> 9;
    int c4  = (rem & 511) * 4;
    const float4* src = (const float4*)((t ? HB : HA) + (size_t)n * KK * CC + c4);
    float4 s = make_float4(0.f, 0.f, 0.f, 0.f);
#pragma unroll 5
    for (int k = 0; k < KK; ++k) {
        float4 e = src[(size_t)k * (CC/4)];
        s.x += e.x; s.y += e.y; s.z += e.z; s.w += e.w;
    }
    *(float4*)(&g_qn[t][n*CC + c4]) = s;
}

// -------- normalize q in place: qn = S / ||S|| --------
__global__ void k_norm() {
    int t = blockIdx.x >> 6, n = blockIdx.x & 63;
    float* p = &g_qn[t][n*CC];
    float ss = 0.f;
    for (int c = threadIdx.x * 4; c < CC; c += 1024) {
        float4 v = *(float4*)(p + c);
        ss += v.x*v.x + v.y*v.y + v.z*v.z + v.w*v.w;
    }
    __shared__ float sm[8];
    for (int o = 16; o; o >>= 1) ss += __shfl_down_sync(~0u, ss, o);
    if ((threadIdx.x & 31) == 0) sm[threadIdx.x >> 5] = ss;
    __syncthreads();
    if (threadIdx.x == 0) {
        float tot = 0.f;
        for (int w = 0; w < 8; ++w) tot += sm[w];
        sm[0] = rsqrtf(tot);
    }
    __syncthreads();
    float inv = sm[0];
    for (int c = threadIdx.x * 4; c < CC; c += 1024) {
        float4 v = *(float4*)(p + c);
        v.x *= inv; v.y *= inv; v.z *= inv; v.w *= inv;
        *(float4*)(p + c) = v;
    }
}

// -------- pass 2: one streaming pass over EA / EB --------
// nce 0: neg = EB with qnA; nce 1: neg = EA with qnB.
// Per (n,k): dot with qn, row norm^2 (warp partials -> global atomics),
// and per-(n,c) column sums into g_SE (for the other nce's l_pos).
// grid: 512 blocks = (i, n, ctile, ksplit); 256 threads * float4 = 1024-float ctile.
__global__ void k_neg(const float* __restrict__ EA, const float* __restrict__ EB) {
    int bx  = blockIdx.x;
    int i   = bx >> 8;
    int rem = bx & 255;
    int n   = rem >> 2;
    int ct  = (rem >> 1) & 1;
    int ks  = rem & 1;
    const float* neg = i ? EA : EB;
    int cbase = ct * 1024 + threadIdx.x * 4;
    float4 q = *(const float4*)(&g_qn[i][n*CC] + cbase);
    const float4* src = (const float4*)(neg + ((size_t)n * KK + ks * 75) * CC + cbase);
    float* dout = &g_dot[i][n*KK + ks*75];
    float* nout = &g_nrm[i][n*KK + ks*75];
    float4 s = make_float4(0.f, 0.f, 0.f, 0.f);
#pragma unroll 5
    for (int k = 0; k < 75; ++k) {
        float4 e = src[(size_t)k * 512];
        s.x += e.x; s.y += e.y; s.z += e.z; s.w += e.w;
        float d  = q.x*e.x + q.y*e.y + q.z*e.z + q.w*e.w;
        float nn = e.x*e.x + e.y*e.y + e.z*e.z + e.w*e.w;
        for (int o = 16; o; o >>= 1) {
            d  += __shfl_down_sync(~0u, d,  o);
            nn += __shfl_down_sync(~0u, nn, o);
        }
        if ((threadIdx.x & 31) == 0) {
            atomicAdd(dout + k, d);
            atomicAdd(nout + k, nn);
        }
    }
    float* se = &g_SE[i][n*CC] + cbase;
    atomicAdd(se + 0, s.x); atomicAdd(se + 1, s.y);
    atomicAdd(se + 2, s.z); atomicAdd(se + 3, s.w);
}

// -------- l_pos[i][n] = qn[i][n] . normalize(SE[1-i][n]) --------
__global__ void k_lpos() {
    int i = blockIdx.x >> 6, n = blockIdx.x & 63;
    const float* q  = &g_qn[i][n*CC];
    const float* se = &g_SE[1 - i][n*CC];
    float d = 0.f, s2 = 0.f;
    for (int c = threadIdx.x * 4; c < CC; c += 1024) {
        float4 qv = *(const float4*)(q + c);
        float4 sv = *(const float4*)(se + c);
        d  += qv.x*sv.x + qv.y*sv.y + qv.z*sv.z + qv.w*sv.w;
        s2 += sv.x*sv.x + sv.y*sv.y + sv.z*sv.z + sv.w*sv.w;
    }
    __shared__ float smd[8], sms[8];
    for (int o = 16; o; o >>= 1) {
        d  += __shfl_down_sync(~0u, d,  o);
        s2 += __shfl_down_sync(~0u, s2, o);
    }
    if ((threadIdx.x & 31) == 0) { smd[threadIdx.x >> 5] = d; sms[threadIdx.x >> 5] = s2; }
    __syncthreads();
    if (threadIdx.x == 0) {
        float D = 0.f, S = 0.f;
        for (int w = 0; w < 8; ++w) { D += smd[w]; S += sms[w]; }
        g_lpos[i][n] = D * rsqrtf(S);
    }
}

// -------- small losses: cls (block 0), rel (blocks 1..8), act (blocks 9..758) --------
__global__ void k_misc(const float* __restrict__ vs,  const float* __restrict__ lab,
                       const float* __restrict__ rs,  const float* __restrict__ rd,
                       const float* __restrict__ a0,  const float* __restrict__ a2) {
    int bx = blockIdx.x, tid = threadIdx.x;
    if (bx == 0) {
        __shared__ float rowsum[BB];
        __shared__ float sm[8];
        if (tid < BB) {
            float s = 0.f;
            for (int c = 0; c < NCC; ++c) s += lab[tid*NCC + c];
            rowsum[tid] = s;
        }
        __syncthreads();
        float acc = 0.f;
        for (int e = tid; e < BB*NCC; e += 256) {
            int n = e / NCC;
            float l = lab[e] / rowsum[n];
            float v = fminf(fmaxf(vs[e], EPSF), 1.f - EPSF);
            acc += l * logf(v) + (1.f - l) * log1pf(-v);
        }
        for (int o = 16; o; o >>= 1) acc += __shfl_down_sync(~0u, acc, o);
        if ((tid & 31) == 0) sm[tid >> 5] = acc;
        __syncthreads();
        if (tid == 0) {
            float t = 0.f;
            for (int w = 0; w < 8; ++w) t += sm[w];
            atomicAdd(&g_acc[0], t);
        }
    } else if (bx <= 8) {
        __shared__ float sma[8], smb[8];
        float ss = 0.f, sd = 0.f;
        for (int e = (bx - 1) * 256 + tid; e < 2*BB*TL; e += 8 * 256) {
            float a = 1.f - rs[e]; ss += a * a;
            float b = rd[e];       sd += b * b;
        }
        for (int o = 16; o; o >>= 1) {
            ss += __shfl_down_sync(~0u, ss, o);
            sd += __shfl_down_sync(~0u, sd, o);
        }
        if ((tid & 31) == 0) { sma[tid >> 5] = ss; smb[tid >> 5] = sd; }
        __syncthreads();
        if (tid == 0) {
            float S = 0.f, D = 0.f;
            for (int w = 0; w < 8; ++w) { S += sma[w]; D += smb[w]; }
            atomicAdd(&g_acc[1], S);
            atomicAdd(&g_acc[2], D);
        }
    } else {
        // loss_act: one block per t; threads 0..63 = batch b.
        int t = bx - 9;
        int b = tid;
        float a0t = 0.f, a2t = 0.f;
        if (b < BB) { a0t = a0[b*TL + t]; a2t = a2[b*TL + t]; }
        __shared__ float sm2[2][2];
        float local = 0.f;
        for (int j = 0; j < 11; ++j) {
            float sq = 0.f, ab = 0.f;
            if (b < BB) {
                int c = t + j - 6; c = c < 0 ? 0 : (c > TL - 1 ? TL - 1 : c);
                float a4 = a0[b*TL + c];
                float a3 = a2[b*TL + c];
                float d0 = a0t - a4; sq = d0 * d0;
                ab = fabsf(a2t - a3);
            }
            for (int o = 16; o; o >>= 1) {
                sq += __shfl_down_sync(~0u, sq, o);
                ab += __shfl_down_sync(~0u, ab, o);
            }
            if (tid == 0 || tid == 32) { sm2[tid >> 5][0] = sq; sm2[tid >> 5][1] = ab; }
            __syncthreads();
            if (tid == 0) {
                float SQ = sm2[0][0] + sm2[1][0];
                float AB = sm2[0][1] + sm2[1][1];
                local += expf(-SQ * 0.5f) * (AB * (1.f / BB));
            }
            __syncthreads();
        }
        if (tid == 0) atomicAdd(&g_acc[3], local);
        float d = (b < BB) ? (a0t - a2t) * (a0t - a2t) : 0.f;
        for (int o = 16; o; o >>= 1) d += __shfl_down_sync(~0u, d, o);
        if (tid == 0 || tid == 32) sm2[tid >> 5][0] = d;
        __syncthreads();
        if (tid == 0) atomicAdd(&g_acc[4], sm2[0][0] + sm2[1][0]);
    }
}

// logit helper for k_final
__device__ __forceinline__ float nce_logit(const float* __restrict__ att,
                                           int i, int n, int e, float logit0) {
    if (e == 0) return logit0;
    int k = e - 1;
    float a  = att[n*300 + i*150 + k];
    float dd = g_dot[i][n*KK + k];
    float nn = g_nrm[i][n*KK + k];
    return a * dd * rsqrtf(nn) * (1.f / T_NCE);
}

// -------- final: softmax losses + combine --------
__global__ void k_final(const float* __restrict__ att, float* __restrict__ out) {
    int wid = threadIdx.x >> 5, lane = threadIdx.x & 31;
    float wloss = 0.f;
    for (int iter = 0; iter < 16; ++iter) {
        int pair = iter * 8 + wid;                 // 0..127 = (i, n)
        int i = pair >> 6, n = pair & 63;
        float logit0 = g_lpos[i][n] * (1.f / T_NCE);
        float mx = -1e30f;
        for (int e = lane; e < 151; e += 32)
            mx = fmaxf(mx, nce_logit(att, i, n, e, logit0));
        for (int o = 16; o; o >>= 1) mx = fmaxf(mx, __shfl_xor_sync(~0u, mx, o));
        float se = 0.f;
        for (int e = lane; e < 151; e += 32)
            se += expf(nce_logit(att, i, n, e, logit0) - mx);
        for (int o = 16; o; o >>= 1) se += __shfl_xor_sync(~0u, se, o);
        if (lane == 0) wloss += logf(se) + mx - logit0;   // -log_softmax[0]
    }
    __shared__ float sm[8];
    if (lane == 0) sm[wid] = wloss;
    __syncthreads();
    if (threadIdx.x == 0) {
        float snico = 0.f;
        for (int w = 0; w < 8; ++w) snico += sm[w];
        snico *= (1.f / BB);                       // mean_n(nce0) + mean_n(nce1)
        float cls = -g_acc[0] * (1.f / (BB * NCC));
        float rel = (g_acc[1] + g_acc[2]) * (1.f / (2 * BB * TL));
        float act = g_acc[3] + 0.1f * g_acc[4] * (1.f / BB);   // E_THETA=0.1, E_ALPHA=1
        float total = cls + 0.01f * snico + act + 0.1f * rel;
        out[0] = total; out[1] = cls; out[2] = snico; out[3] = act; out[4] = rel;
    }
}

extern "C" void kernel_launch(void* const* d_in, const int* in_sizes, int n_in,
                              void* d_out, int out_size) {
    const float* video = (const float*)d_in[0];   // (B,NC)
    const float* label = (const float*)d_in[1];   // (B,NC)
    const float* HA    = (const float*)d_in[2];   // (B,K,C)
    const float* EA    = (const float*)d_in[3];
    const float* HB    = (const float*)d_in[4];
    const float* EB    = (const float*)d_in[5];
    const float* rs    = (const float*)d_in[6];   // (2,B,TL)
    const float* rd    = (const float*)d_in[7];
    const float* a0    = (const float*)d_in[8];   // (B,TL)
    const float* a2    = (const float*)d_in[9];
    const float* att   = (const float*)d_in[10];  // (B,300,1)
    float* out = (float*)d_out;

    k_zero<<<(2*BB*CC + 255) / 256, 256>>>();
    k_qsum<<<256, 256>>>(HA, HB);
    k_misc<<<9 + TL, 256>>>(video, label, rs, rd, a0, a2);
    k_norm<<<128, 256>>>();
    k_neg<<<512, 256>>>(EA, EB);
    k_lpos<<<128, 256>>>();
    k_final<<<1, 256>>>(att, out);
    (void)in_sizes; (void)n_in; (void)out_size;
}

// round 4
// speedup vs baseline: 2.0246x; 2.0246x over previous
#include <cuda_runtime.h>
#include <math.h>

#define BB   64
#define NCC  20
#define KK   150
#define CC   2048
#define C4   (CC/4)
#define TL   750
#define T_NCE 0.07f
#define EPSF  1e-7f

// ---------------- scratch (device globals; unique writer per slot, no zeroing needed) ----
__device__ float4 g_Sp [4][2][BB*C4];   // pass1: K-chunk partial column sums of HA/HB
__device__ float4 g_SEp[8][2][BB*C4];   // pass2: K-chunk partial column sums of EB/EA
__device__ float  g_dot[2][BB*KK];      // raw S_i . e_k
__device__ float  g_nrm[2][BB*KK];      // ||e_k||^2
__device__ float  g_nce[2*BB];
__device__ float  g_cls;
__device__ float  g_rel[8][2];
__device__ float  g_actw[TL];
__device__ float  g_acts[TL];

// ================= k1: stream HA,HB (157 MB) -> g_Sp; plus cls/rel/act losses =========
// blocks [0,1024): qsum  (t,n,ct,ks) ; 1024: cls ; 1025..1032: rel ; 1033..1220: act
__global__ void __launch_bounds__(256) k1(
    const float* __restrict__ HA, const float* __restrict__ HB,
    const float* __restrict__ vs, const float* __restrict__ lab,
    const float* __restrict__ rs, const float* __restrict__ rd,
    const float* __restrict__ a0, const float* __restrict__ a2)
{
    int bx = blockIdx.x, tid = threadIdx.x;
    if (bx < 1024) {
        int t = bx >> 9, rem = bx & 511;
        int n = rem >> 3, ct = (rem >> 2) & 1, ks = rem & 3;
        int k0 = (ks * KK) >> 2, k1e = ((ks + 1) * KK) >> 2;
        int c4 = ct * 256 + tid;
        const float4* src = (const float4*)(t ? HB : HA) + (size_t)(n * KK + k0) * C4 + c4;
        float4 s = make_float4(0.f, 0.f, 0.f, 0.f);
#pragma unroll 4
        for (int k = k0; k < k1e; ++k) {
            float4 e = __ldcs(src); src += C4;
            s.x += e.x; s.y += e.y; s.z += e.z; s.w += e.w;
        }
        g_Sp[ks][t][n * C4 + c4] = s;
    } else if (bx == 1024) {
        // loss_cls
        __shared__ float rowsum[BB];
        __shared__ float sm[8];
        if (tid < BB) {
            float s = 0.f;
            for (int c = 0; c < NCC; ++c) s += lab[tid * NCC + c];
            rowsum[tid] = s;
        }
        __syncthreads();
        float acc = 0.f;
        for (int e = tid; e < BB * NCC; e += 256) {
            int n = e / NCC;
            float l = lab[e] / rowsum[n];
            float v = fminf(fmaxf(vs[e], EPSF), 1.f - EPSF);
            acc += l * logf(v) + (1.f - l) * log1pf(-v);
        }
        for (int o = 16; o; o >>= 1) acc += __shfl_down_sync(~0u, acc, o);
        if ((tid & 31) == 0) sm[tid >> 5] = acc;
        __syncthreads();
        if (tid == 0) {
            float t2 = 0.f;
            for (int w = 0; w < 8; ++w) t2 += sm[w];
            g_cls = t2;
        }
    } else if (bx <= 1032) {
        // loss_rel partials
        int blk = bx - 1025;
        __shared__ float sma[8], smb[8];
        float ss = 0.f, sd = 0.f;
        for (int e = blk * 256 + tid; e < 2 * BB * TL; e += 8 * 256) {
            float a = 1.f - rs[e]; ss += a * a;
            float b = rd[e];       sd += b * b;
        }
        for (int o = 16; o; o >>= 1) {
            ss += __shfl_down_sync(~0u, ss, o);
            sd += __shfl_down_sync(~0u, sd, o);
        }
        if ((tid & 31) == 0) { sma[tid >> 5] = ss; smb[tid >> 5] = sd; }
        __syncthreads();
        if (tid == 0) {
            float S = 0.f, D = 0.f;
            for (int w = 0; w < 8; ++w) { S += sma[w]; D += smb[w]; }
            g_rel[blk][0] = S; g_rel[blk][1] = D;
        }
    } else {
        // loss_act: 4 time-steps per block; 64 lanes = batch
        int tg = tid >> 6;            // 0..3
        int b  = tid & 63;
        int hf = (tid >> 5) & 1;      // warp-in-group
        int t  = (bx - 1033) * 4 + tg;
        bool valid = t < TL;
        float a0t = valid ? a0[b * TL + t] : 0.f;
        float a2t = valid ? a2[b * TL + t] : 0.f;
        __shared__ float smq[4][2], sma2[4][2];
        float local = 0.f;
        for (int j = 0; j < 11; ++j) {
            float sq = 0.f, ab = 0.f;
            if (valid) {
                int c = t + j - 6; c = c < 0 ? 0 : (c > TL - 1 ? TL - 1 : c);
                float d0 = a0t - a0[b * TL + c]; sq = d0 * d0;
                ab = fabsf(a2t - a2[b * TL + c]);
            }
            for (int o = 16; o; o >>= 1) {
                sq += __shfl_down_sync(~0u, sq, o);
                ab += __shfl_down_sync(~0u, ab, o);
            }
            if ((tid & 31) == 0) { smq[tg][hf] = sq; sma2[tg][hf] = ab; }
            __syncthreads();
            if ((tid & 63) == 0) {
                float SQ = smq[tg][0] + smq[tg][1];
                float AB = sma2[tg][0] + sma2[tg][1];
                local += expf(-0.5f * SQ) * (AB * (1.f / BB));
            }
            __syncthreads();
        }
        if ((tid & 63) == 0 && valid) g_actw[t] = local;
        float d = valid ? (a0t - a2t) * (a0t - a2t) : 0.f;
        for (int o = 16; o; o >>= 1) d += __shfl_down_sync(~0u, d, o);
        if ((tid & 31) == 0) smq[tg][hf] = d;
        __syncthreads();
        if ((tid & 63) == 0 && valid) g_acts[t] = smq[tg][0] + smq[tg][1];
    }
}

// ================= k2: stream EA,EB (157 MB) -> raw dots, norms, SE partials ==========
// 1024 blocks = (i, n, ks); each warp covers a full 2048-float row (lanes own c4=tid, tid+256)
__global__ void __launch_bounds__(256) k2(const float* __restrict__ EA,
                                          const float* __restrict__ EB)
{
    int bx = blockIdx.x, tid = threadIdx.x;
    int i = bx >> 9, rem = bx & 511;
    int n = rem >> 3, ks = rem & 7;
    int k0 = (ks * KK) >> 3, k1e = ((ks + 1) * KK) >> 3;
    int wid = tid >> 5, lane = tid & 31;

    // q = raw S_i[n] (sum of 4 K-chunk partials)
    float4 q0 = make_float4(0.f, 0.f, 0.f, 0.f), q1 = q0;
#pragma unroll
    for (int p = 0; p < 4; ++p) {
        float4 a = g_Sp[p][i][n * C4 + tid];
        float4 b = g_Sp[p][i][n * C4 + 256 + tid];
        q0.x += a.x; q0.y += a.y; q0.z += a.z; q0.w += a.w;
        q1.x += b.x; q1.y += b.y; q1.z += b.z; q1.w += b.w;
    }

    const float4* src = (const float4*)(i ? EA : EB) + (size_t)(n * KK + k0) * C4;
    __shared__ float sd[19][8], sn[19][8];
    float4 s0 = make_float4(0.f, 0.f, 0.f, 0.f), s1 = s0;

#pragma unroll 2
    for (int k = k0; k < k1e; ++k) {
        float4 e0 = __ldcs(src + tid);
        float4 e1 = __ldcs(src + 256 + tid);
        src += C4;
        s0.x += e0.x; s0.y += e0.y; s0.z += e0.z; s0.w += e0.w;
        s1.x += e1.x; s1.y += e1.y; s1.z += e1.z; s1.w += e1.w;
        float d  = q0.x*e0.x + q0.y*e0.y + q0.z*e0.z + q0.w*e0.w
                 + q1.x*e1.x + q1.y*e1.y + q1.z*e1.z + q1.w*e1.w;
        float nn = e0.x*e0.x + e0.y*e0.y + e0.z*e0.z + e0.w*e0.w
                 + e1.x*e1.x + e1.y*e1.y + e1.z*e1.z + e1.w*e1.w;
        for (int o = 16; o; o >>= 1) {
            d  += __shfl_down_sync(~0u, d,  o);
            nn += __shfl_down_sync(~0u, nn, o);
        }
        if (lane == 0) { sd[k - k0][wid] = d; sn[k - k0][wid] = nn; }
    }
    __syncthreads();
    int cnt = k1e - k0;
    if (tid < cnt) {
        float D = 0.f;
#pragma unroll
        for (int w = 0; w < 8; ++w) D += sd[tid][w];
        g_dot[i][n * KK + k0 + tid] = D;
    } else if (tid >= 64 && tid < 64 + cnt) {
        int kk = tid - 64;
        float N = 0.f;
#pragma unroll
        for (int w = 0; w < 8; ++w) N += sn[kk][w];
        g_nrm[i][n * KK + k0 + kk] = N;
    }
    g_SEp[ks][i][n * C4 + tid] = s0;
    g_SEp[ks][i][n * C4 + 256 + tid] = s1;
}

// ================= k3: per-(i,n) NCE loss (lpos + softmax over 151 logits) ============
__global__ void __launch_bounds__(256) k3(const float* __restrict__ att)
{
    int i = blockIdx.x >> 6, n = blockIdx.x & 63;
    int tid = threadIdx.x, wid = tid >> 5, lane = tid & 31;

    float4 S0 = make_float4(0.f,0.f,0.f,0.f), S1 = S0, E0 = S0, E1 = S0;
#pragma unroll
    for (int p = 0; p < 4; ++p) {
        float4 a = g_Sp[p][i][n * C4 + tid];
        float4 b = g_Sp[p][i][n * C4 + 256 + tid];
        S0.x += a.x; S0.y += a.y; S0.z += a.z; S0.w += a.w;
        S1.x += b.x; S1.y += b.y; S1.z += b.z; S1.w += b.w;
    }
#pragma unroll
    for (int p = 0; p < 8; ++p) {
        float4 a = g_SEp[p][1 - i][n * C4 + tid];
        float4 b = g_SEp[p][1 - i][n * C4 + 256 + tid];
        E0.x += a.x; E0.y += a.y; E0.z += a.z; E0.w += a.w;
        E1.x += b.x; E1.y += b.y; E1.z += b.z; E1.w += b.w;
    }
    float qss  = S0.x*S0.x+S0.y*S0.y+S0.z*S0.z+S0.w*S0.w + S1.x*S1.x+S1.y*S1.y+S1.z*S1.z+S1.w*S1.w;
    float sess = E0.x*E0.x+E0.y*E0.y+E0.z*E0.z+E0.w*E0.w + E1.x*E1.x+E1.y*E1.y+E1.z*E1.z+E1.w*E1.w;
    float dse  = S0.x*E0.x+S0.y*E0.y+S0.z*E0.z+S0.w*E0.w + S1.x*E1.x+S1.y*E1.y+S1.z*E1.z+S1.w*E1.w;

    __shared__ float sm[8][3];
    __shared__ float bc[2];
    for (int o = 16; o; o >>= 1) {
        qss  += __shfl_down_sync(~0u, qss,  o);
        sess += __shfl_down_sync(~0u, sess, o);
        dse  += __shfl_down_sync(~0u, dse,  o);
    }
    if (lane == 0) { sm[wid][0] = qss; sm[wid][1] = sess; sm[wid][2] = dse; }
    __syncthreads();
    if (tid == 0) {
        float Q = 0.f, S = 0.f, D = 0.f;
        for (int w = 0; w < 8; ++w) { Q += sm[w][0]; S += sm[w][1]; D += sm[w][2]; }
        float rq = rsqrtf(Q);
        bc[0] = rq;
        bc[1] = D * rq * rsqrtf(S) * (1.f / T_NCE);    // logit0
    }
    __syncthreads();
    float rq = bc[0], logit0 = bc[1];

    float logit = -1e30f;
    if (tid == 0) logit = logit0;
    else if (tid <= 150) {
        int k = tid - 1;
        logit = att[n * 300 + i * 150 + k] * g_dot[i][n * KK + k] * rq
              * rsqrtf(g_nrm[i][n * KK + k]) * (1.f / T_NCE);
    }
    // block max
    float mx = logit;
    for (int o = 16; o; o >>= 1) mx = fmaxf(mx, __shfl_xor_sync(~0u, mx, o));
    if (lane == 0) sm[wid][0] = mx;
    __syncthreads();
    if (tid == 0) {
        float M = -1e30f;
        for (int w = 0; w < 8; ++w) M = fmaxf(M, sm[w][0]);
        bc[0] = M;
    }
    __syncthreads();
    float M = bc[0];
    float ex = (tid <= 150) ? expf(logit - M) : 0.f;
    for (int o = 16; o; o >>= 1) ex += __shfl_down_sync(~0u, ex, o);
    if (lane == 0) sm[wid][1] = ex;
    __syncthreads();
    if (tid == 0) {
        float SE = 0.f;
        for (int w = 0; w < 8; ++w) SE += sm[w][1];
        g_nce[i * 64 + n] = logf(SE) + M - logit0;     // -log_softmax[0]
    }
}

// ================= k4: combine scalars ================================================
__global__ void __launch_bounds__(256) k4(float* __restrict__ out)
{
    int tid = threadIdx.x, wid = tid >> 5, lane = tid & 31;
    float sn = 0.f, sw = 0.f, ss = 0.f, sr = 0.f;
    for (int e = tid; e < 2 * BB; e += 256) sn += g_nce[e];
    for (int e = tid; e < TL; e += 256) { sw += g_actw[e]; ss += g_acts[e]; }
    if (tid < 16) sr = g_rel[tid >> 1][tid & 1];
    __shared__ float sm[8][4];
    for (int o = 16; o; o >>= 1) {
        sn += __shfl_down_sync(~0u, sn, o);
        sw += __shfl_down_sync(~0u, sw, o);
        ss += __shfl_down_sync(~0u, ss, o);
        sr += __shfl_down_sync(~0u, sr, o);
    }
    if (lane == 0) { sm[wid][0]=sn; sm[wid][1]=sw; sm[wid][2]=ss; sm[wid][3]=sr; }
    __syncthreads();
    if (tid == 0) {
        float SN=0.f, SW=0.f, SS=0.f, SR=0.f;
        for (int w = 0; w < 8; ++w) { SN+=sm[w][0]; SW+=sm[w][1]; SS+=sm[w][2]; SR+=sm[w][3]; }
        float cls   = -g_cls * (1.f / (BB * NCC));
        float rel   = SR * (1.f / (2 * BB * TL));
        float act   = SW + 0.1f * SS * (1.f / BB);     // E_THETA=0.1, E_ALPHA=1
        float snico = SN * (1.f / BB);
        out[0] = cls + 0.01f * snico + act + 0.1f * rel;
        out[1] = cls; out[2] = snico; out[3] = act; out[4] = rel;
    }
}

extern "C" void kernel_launch(void* const* d_in, const int* in_sizes, int n_in,
                              void* d_out, int out_size) {
    const float* video = (const float*)d_in[0];
    const float* label = (const float*)d_in[1];
    const float* HA    = (const float*)d_in[2];
    const float* EA    = (const float*)d_in[3];
    const float* HB    = (const float*)d_in[4];
    const float* EB    = (const float*)d_in[5];
    const float* rs    = (const float*)d_in[6];
    const float* rd    = (const float*)d_in[7];
    const float* a0    = (const float*)d_in[8];
    const float* a2    = (const float*)d_in[9];
    const float* att   = (const float*)d_in[10];
    float* out = (float*)d_out;

    k1<<<1033 + 188, 256>>>(HA, HB, video, label, rs, rd, a0, a2);
    k2<<<1024, 256>>>(EA, EB);
    k3<<<128, 256>>>(att);
    k4<<<1, 256>>>(out);
    (void)in_sizes; (void)n_in; (void)out_size;
}

// round 5
// speedup vs baseline: 2.0282x; 1.0018x over previous
#include <cuda_runtime.h>
#include <math.h>

#define BB   64
#define NCC  20
#define KK   150
#define CC   2048
#define C4   (CC/4)
#define TL   750
#define T_NCE 0.07f
#define EPSF  1e-7f

// ---------------- scratch (device globals; unique writer per slot, no zeroing needed) ----
__device__ float4 g_Sp [4][2][BB*C4];   // pass1: K-chunk partial column sums of HA/HB
__device__ float4 g_SEp[8][2][BB*C4];   // pass2: K-chunk partial column sums of EB/EA
__device__ float  g_dot[2][BB*KK];      // raw S_i . e_k
__device__ float  g_nrm[2][BB*KK];      // ||e_k||^2
__device__ float  g_nce[2*BB];
__device__ float  g_cls;
__device__ float  g_rel[8][2];
__device__ float  g_actw[TL];
__device__ float  g_acts[TL];
__device__ unsigned int g_ctr = 0;      // last-block counter (self-resetting each replay)

// ================= k1: stream HA,HB (157 MB) -> g_Sp; plus cls/rel/act losses =========
// blocks [0,1024): qsum  (t,n,ct,ks) ; 1024: cls ; 1025..1032: rel ; 1033..1220: act
__global__ void __launch_bounds__(256) k1(
    const float* __restrict__ HA, const float* __restrict__ HB,
    const float* __restrict__ vs, const float* __restrict__ lab,
    const float* __restrict__ rs, const float* __restrict__ rd,
    const float* __restrict__ a0, const float* __restrict__ a2)
{
    int bx = blockIdx.x, tid = threadIdx.x;
    if (bx < 1024) {
        int t = bx >> 9, rem = bx & 511;
        int n = rem >> 3, ct = (rem >> 2) & 1, ks = rem & 3;
        int k0 = (ks * KK) >> 2, k1e = ((ks + 1) * KK) >> 2;
        int c4 = ct * 256 + tid;
        const float4* src = (const float4*)(t ? HB : HA) + (size_t)(n * KK + k0) * C4 + c4;
        float4 sa = make_float4(0.f, 0.f, 0.f, 0.f);
        float4 sb = make_float4(0.f, 0.f, 0.f, 0.f);
        int k = k0;
#pragma unroll 4
        for (; k + 1 < k1e; k += 2) {
            float4 e0 = __ldcs(src);       src += C4;
            float4 e1 = __ldcs(src);       src += C4;
            sa.x += e0.x; sa.y += e0.y; sa.z += e0.z; sa.w += e0.w;
            sb.x += e1.x; sb.y += e1.y; sb.z += e1.z; sb.w += e1.w;
        }
        if (k < k1e) {
            float4 e0 = __ldcs(src);
            sa.x += e0.x; sa.y += e0.y; sa.z += e0.z; sa.w += e0.w;
        }
        sa.x += sb.x; sa.y += sb.y; sa.z += sb.z; sa.w += sb.w;
        g_Sp[ks][t][n * C4 + c4] = sa;
    } else if (bx == 1024) {
        // loss_cls
        __shared__ float rowsum[BB];
        __shared__ float sm[8];
        if (tid < BB) {
            float s = 0.f;
            for (int c = 0; c < NCC; ++c) s += lab[tid * NCC + c];
            rowsum[tid] = s;
        }
        __syncthreads();
        float acc = 0.f;
        for (int e = tid; e < BB * NCC; e += 256) {
            int n = e / NCC;
            float l = lab[e] / rowsum[n];
            float v = fminf(fmaxf(vs[e], EPSF), 1.f - EPSF);
            acc += l * logf(v) + (1.f - l) * log1pf(-v);
        }
        for (int o = 16; o; o >>= 1) acc += __shfl_down_sync(~0u, acc, o);
        if ((tid & 31) == 0) sm[tid >> 5] = acc;
        __syncthreads();
        if (tid == 0) {
            float t2 = 0.f;
            for (int w = 0; w < 8; ++w) t2 += sm[w];
            g_cls = t2;
        }
    } else if (bx <= 1032) {
        // loss_rel partials
        int blk = bx - 1025;
        __shared__ float sma[8], smb[8];
        float ss = 0.f, sd = 0.f;
        for (int e = blk * 256 + tid; e < 2 * BB * TL; e += 8 * 256) {
            float a = 1.f - rs[e]; ss += a * a;
            float b = rd[e];       sd += b * b;
        }
        for (int o = 16; o; o >>= 1) {
            ss += __shfl_down_sync(~0u, ss, o);
            sd += __shfl_down_sync(~0u, sd, o);
        }
        if ((tid & 31) == 0) { sma[tid >> 5] = ss; smb[tid >> 5] = sd; }
        __syncthreads();
        if (tid == 0) {
            float S = 0.f, D = 0.f;
            for (int w = 0; w < 8; ++w) { S += sma[w]; D += smb[w]; }
            g_rel[blk][0] = S; g_rel[blk][1] = D;
        }
    } else {
        // loss_act: 4 time-steps per block; 64 lanes = batch
        int tg = tid >> 6;            // 0..3
        int b  = tid & 63;
        int hf = (tid >> 5) & 1;      // warp-in-group
        int t  = (bx - 1033) * 4 + tg;
        bool valid = t < TL;
        float a0t = valid ? a0[b * TL + t] : 0.f;
        float a2t = valid ? a2[b * TL + t] : 0.f;
        __shared__ float smq[4][2], sma2[4][2];
        float local = 0.f;
        for (int j = 0; j < 11; ++j) {
            float sq = 0.f, ab = 0.f;
            if (valid) {
                int c = t + j - 6; c = c < 0 ? 0 : (c > TL - 1 ? TL - 1 : c);
                float d0 = a0t - a0[b * TL + c]; sq = d0 * d0;
                ab = fabsf(a2t - a2[b * TL + c]);
            }
            for (int o = 16; o; o >>= 1) {
                sq += __shfl_down_sync(~0u, sq, o);
                ab += __shfl_down_sync(~0u, ab, o);
            }
            if ((tid & 31) == 0) { smq[tg][hf] = sq; sma2[tg][hf] = ab; }
            __syncthreads();
            if ((tid & 63) == 0) {
                float SQ = smq[tg][0] + smq[tg][1];
                float AB = sma2[tg][0] + sma2[tg][1];
                local += expf(-0.5f * SQ) * (AB * (1.f / BB));
            }
            __syncthreads();
        }
        if ((tid & 63) == 0 && valid) g_actw[t] = local;
        float d = valid ? (a0t - a2t) * (a0t - a2t) : 0.f;
        for (int o = 16; o; o >>= 1) d += __shfl_down_sync(~0u, d, o);
        if ((tid & 31) == 0) smq[tg][hf] = d;
        __syncthreads();
        if ((tid & 63) == 0 && valid) g_acts[t] = smq[tg][0] + smq[tg][1];
    }
}

// ================= k2: stream EA,EB (157 MB) -> raw dots, norms, SE partials ==========
// 1024 blocks = (i, n, ks); block covers a full 2048-float row; pipelined loads.
__global__ void __launch_bounds__(256) k2(const float* __restrict__ EA,
                                          const float* __restrict__ EB)
{
    int bx = blockIdx.x, tid = threadIdx.x;
    int i = bx >> 9, rem = bx & 511;
    int n = rem >> 3, ks = rem & 7;
    int k0 = (ks * KK) >> 3, k1e = ((ks + 1) * KK) >> 3;
    int wid = tid >> 5, lane = tid & 31;

    // q = raw S_i[n] (sum of 4 K-chunk partials)
    float4 q0 = make_float4(0.f, 0.f, 0.f, 0.f), q1 = q0;
#pragma unroll
    for (int p = 0; p < 4; ++p) {
        float4 a = g_Sp[p][i][n * C4 + tid];
        float4 b = g_Sp[p][i][n * C4 + 256 + tid];
        q0.x += a.x; q0.y += a.y; q0.z += a.z; q0.w += a.w;
        q1.x += b.x; q1.y += b.y; q1.z += b.z; q1.w += b.w;
    }

    const float4* src = (const float4*)(i ? EA : EB) + (size_t)(n * KK + k0) * C4;
    __shared__ float sd[19][8], sn[19][8];
    float4 s0 = make_float4(0.f, 0.f, 0.f, 0.f), s1 = s0;

    int cnt = k1e - k0;
    // prologue load
    float4 e0 = __ldcs(src + tid);
    float4 e1 = __ldcs(src + 256 + tid);
    src += C4;
    for (int k = 0; k < cnt; ++k) {
        float4 f0, f1;
        if (k + 1 < cnt) {                 // prefetch next row before reducing this one
            f0 = __ldcs(src + tid);
            f1 = __ldcs(src + 256 + tid);
            src += C4;
        }
        s0.x += e0.x; s0.y += e0.y; s0.z += e0.z; s0.w += e0.w;
        s1.x += e1.x; s1.y += e1.y; s1.z += e1.z; s1.w += e1.w;
        float d  = q0.x*e0.x + q0.y*e0.y + q0.z*e0.z + q0.w*e0.w
                 + q1.x*e1.x + q1.y*e1.y + q1.z*e1.z + q1.w*e1.w;
        float nn = e0.x*e0.x + e0.y*e0.y + e0.z*e0.z + e0.w*e0.w
                 + e1.x*e1.x + e1.y*e1.y + e1.z*e1.z + e1.w*e1.w;
        for (int o = 16; o; o >>= 1) {
            d  += __shfl_down_sync(~0u, d,  o);
            nn += __shfl_down_sync(~0u, nn, o);
        }
        if (lane == 0) { sd[k][wid] = d; sn[k][wid] = nn; }
        e0 = f0; e1 = f1;
    }
    __syncthreads();
    if (tid < cnt) {
        float D = 0.f;
#pragma unroll
        for (int w = 0; w < 8; ++w) D += sd[tid][w];
        g_dot[i][n * KK + k0 + tid] = D;
    } else if (tid >= 64 && tid < 64 + cnt) {
        int kk = tid - 64;
        float N = 0.f;
#pragma unroll
        for (int w = 0; w < 8; ++w) N += sn[kk][w];
        g_nrm[i][n * KK + k0 + kk] = N;
    }
    g_SEp[ks][i][n * C4 + tid] = s0;
    g_SEp[ks][i][n * C4 + 256 + tid] = s1;
}

// ================= k3: per-(i,n) NCE loss; last block combines everything ============
__global__ void __launch_bounds__(256) k3(const float* __restrict__ att,
                                          float* __restrict__ out)
{
    int i = blockIdx.x >> 6, n = blockIdx.x & 63;
    int tid = threadIdx.x, wid = tid >> 5, lane = tid & 31;

    float4 S0 = make_float4(0.f,0.f,0.f,0.f), S1 = S0, E0 = S0, E1 = S0;
#pragma unroll
    for (int p = 0; p < 4; ++p) {
        float4 a = g_Sp[p][i][n * C4 + tid];
        float4 b = g_Sp[p][i][n * C4 + 256 + tid];
        S0.x += a.x; S0.y += a.y; S0.z += a.z; S0.w += a.w;
        S1.x += b.x; S1.y += b.y; S1.z += b.z; S1.w += b.w;
    }
#pragma unroll
    for (int p = 0; p < 8; ++p) {
        float4 a = g_SEp[p][1 - i][n * C4 + tid];
        float4 b = g_SEp[p][1 - i][n * C4 + 256 + tid];
        E0.x += a.x; E0.y += a.y; E0.z += a.z; E0.w += a.w;
        E1.x += b.x; E1.y += b.y; E1.z += b.z; E1.w += b.w;
    }
    float qss  = S0.x*S0.x+S0.y*S0.y+S0.z*S0.z+S0.w*S0.w + S1.x*S1.x+S1.y*S1.y+S1.z*S1.z+S1.w*S1.w;
    float sess = E0.x*E0.x+E0.y*E0.y+E0.z*E0.z+E0.w*E0.w + E1.x*E1.x+E1.y*E1.y+E1.z*E1.z+E1.w*E1.w;
    float dse  = S0.x*E0.x+S0.y*E0.y+S0.z*E0.z+S0.w*E0.w + S1.x*E1.x+S1.y*E1.y+S1.z*E1.z+S1.w*E1.w;

    __shared__ float sm[8][4];
    __shared__ float bc[2];
    for (int o = 16; o; o >>= 1) {
        qss  += __shfl_down_sync(~0u, qss,  o);
        sess += __shfl_down_sync(~0u, sess, o);
        dse  += __shfl_down_sync(~0u, dse,  o);
    }
    if (lane == 0) { sm[wid][0] = qss; sm[wid][1] = sess; sm[wid][2] = dse; }
    __syncthreads();
    if (tid == 0) {
        float Q = 0.f, S = 0.f, D = 0.f;
        for (int w = 0; w < 8; ++w) { Q += sm[w][0]; S += sm[w][1]; D += sm[w][2]; }
        float rq = rsqrtf(Q);
        bc[0] = rq;
        bc[1] = D * rq * rsqrtf(S) * (1.f / T_NCE);    // logit0
    }
    __syncthreads();
    float rq = bc[0], logit0 = bc[1];

    float logit = -1e30f;
    if (tid == 0) logit = logit0;
    else if (tid <= 150) {
        int k = tid - 1;
        logit = att[n * 300 + i * 150 + k] * g_dot[i][n * KK + k] * rq
              * rsqrtf(g_nrm[i][n * KK + k]) * (1.f / T_NCE);
    }
    // block max
    float mx = logit;
    for (int o = 16; o; o >>= 1) mx = fmaxf(mx, __shfl_xor_sync(~0u, mx, o));
    if (lane == 0) sm[wid][0] = mx;
    __syncthreads();
    if (tid == 0) {
        float M = -1e30f;
        for (int w = 0; w < 8; ++w) M = fmaxf(M, sm[w][0]);
        bc[0] = M;
    }
    __syncthreads();
    float M = bc[0];
    float ex = (tid <= 150) ? expf(logit - M) : 0.f;
    for (int o = 16; o; o >>= 1) ex += __shfl_down_sync(~0u, ex, o);
    if (lane == 0) sm[wid][1] = ex;
    __syncthreads();
    if (tid == 0) {
        float SE = 0.f;
        for (int w = 0; w < 8; ++w) SE += sm[w][1];
        g_nce[i * 64 + n] = logf(SE) + M - logit0;     // -log_softmax[0]
    }

    // ---- last-block final combine (replaces k4) ----
    __shared__ unsigned last;
    __threadfence();
    __syncthreads();
    if (tid == 0) last = (atomicAdd(&g_ctr, 1u) == (unsigned)(gridDim.x - 1)) ? 1u : 0u;
    __syncthreads();
    if (!last) return;
    __threadfence();   // acquire: see all blocks' g_nce writes

    float sn2 = 0.f, sw = 0.f, ss = 0.f, sr = 0.f;
    for (int e = tid; e < 2 * BB; e += 256) sn2 += g_nce[e];
    for (int e = tid; e < TL; e += 256) { sw += g_actw[e]; ss += g_acts[e]; }
    if (tid < 16) sr = g_rel[tid >> 1][tid & 1];
    for (int o = 16; o; o >>= 1) {
        sn2 += __shfl_down_sync(~0u, sn2, o);
        sw  += __shfl_down_sync(~0u, sw,  o);
        ss  += __shfl_down_sync(~0u, ss,  o);
        sr  += __shfl_down_sync(~0u, sr,  o);
    }
    if (lane == 0) { sm[wid][0]=sn2; sm[wid][1]=sw; sm[wid][2]=ss; sm[wid][3]=sr; }
    __syncthreads();
    if (tid == 0) {
        float SN=0.f, SW=0.f, SS=0.f, SR=0.f;
        for (int w = 0; w < 8; ++w) { SN+=sm[w][0]; SW+=sm[w][1]; SS+=sm[w][2]; SR+=sm[w][3]; }
        float cls   = -g_cls * (1.f / (BB * NCC));
        float rel   = SR * (1.f / (2 * BB * TL));
        float act   = SW + 0.1f * SS * (1.f / BB);     // E_THETA=0.1, E_ALPHA=1
        float snico = SN * (1.f / BB);
        out[0] = cls + 0.01f * snico + act + 0.1f * rel;
        out[1] = cls; out[2] = snico; out[3] = act; out[4] = rel;
        g_ctr = 0;                                     // reset for next graph replay
    }
}

extern "C" void kernel_launch(void* const* d_in, const int* in_sizes, int n_in,
                              void* d_out, int out_size) {
    const float* video = (const float*)d_in[0];
    const float* label = (const float*)d_in[1];
    const float* HA    = (const float*)d_in[2];
    const float* EA    = (const float*)d_in[3];
    const float* HB    = (const float*)d_in[4];
    const float* EB    = (const float*)d_in[5];
    const float* rs    = (const float*)d_in[6];
    const float* rd    = (const float*)d_in[7];
    const float* a0    = (const float*)d_in[8];
    const float* a2    = (const float*)d_in[9];
    const float* att   = (const float*)d_in[10];
    float* out = (float*)d_out;

    k1<<<1033 + 188, 256>>>(HA, HB, video, label, rs, rd, a0, a2);
    k2<<<1024, 256>>>(EA, EB);
    k3<<<128, 256>>>(att, out);
    (void)in_sizes; (void)n_in; (void)out_size;
}